// round 6
// baseline (speedup 1.0000x reference)
#include <cuda_runtime.h>
#include <cuda_bf16.h>
#include <cstdint>

#define MAXN 100000
#define MAXE 1600000
#define F 128

// ---------------- scratch (static device globals; no allocs allowed) ----------
__device__ int   g_cnt[MAXN];                // degree counts
__device__ int   g_off[MAXN + 1];            // CSR offsets (by dst)
__device__ int   g_cur[MAXN];                // scatter cursors
__device__ int   g_csr[MAXE];                // src node per CSR slot
__device__ float g_mean[(size_t)MAXN * F];   // aggregated means (reused both layers)
__device__ float g_h[(size_t)MAXN * F];      // layer-1 activations

// ---------------- CSR build --------------------------------------------------
__global__ void k_zero_cnt(int n) {
    int i = blockIdx.x * 256 + threadIdx.x;
    if (i < n) g_cnt[i] = 0;
}

// edge_index is int32 (JAX default x64-disabled downcasts int64 -> int32)
__global__ void k_hist(const int* __restrict__ dst, int E, int n) {
    int e = blockIdx.x * 256 + threadIdx.x;
    if (e < E) {
        int d = dst[e];
        if ((unsigned)d < (unsigned)n) atomicAdd(&g_cnt[d], 1);
    }
}

// single-block scan over n counts -> exclusive offsets, also zero cursors
__global__ void k_scan(int n) {
    __shared__ int part[1024];
    int t = threadIdx.x;
    int chunk = (n + 1023) / 1024;
    int s = t * chunk;
    int e = min(s + chunk, n);
    int sum = 0;
    for (int i = s; i < e; i++) sum += g_cnt[i];
    part[t] = sum;
    __syncthreads();
    for (int d = 1; d < 1024; d <<= 1) {
        int v = (t >= d) ? part[t - d] : 0;
        __syncthreads();
        part[t] += v;
        __syncthreads();
    }
    int run = (t == 0) ? 0 : part[t - 1];
    for (int i = s; i < e; i++) {
        g_off[i] = run;
        run += g_cnt[i];
        g_cur[i] = 0;
    }
    if (t == 0) g_off[n] = part[1023];
}

__global__ void k_scatter(const int* __restrict__ src,
                          const int* __restrict__ dst, int E, int n) {
    int e = blockIdx.x * 256 + threadIdx.x;
    if (e < E) {
        int d = dst[e];
        int s = src[e];
        if ((unsigned)d < (unsigned)n && (unsigned)s < (unsigned)n) {
            int p = g_off[d] + atomicAdd(&g_cur[d], 1);
            g_csr[p] = s;
        }
    }
}

// ---------------- mean aggregation (CSR, no atomics) -------------------------
// 8 nodes per 256-thread block; 32 lanes per node; each lane owns 4 channels.
// use_gh: 0 -> read from feat_in (harness x), 1 -> read from g_h (scratch).
__global__ void k_agg(const float* __restrict__ feat_in, int use_gh, int n) {
    int node = blockIdx.x * 8 + (threadIdx.x >> 5);
    int lane = threadIdx.x & 31;
    if (node >= n) return;
    const float* feat = use_gh ? (const float*)g_h : feat_in;
    int beg = g_off[node];
    int end = g_off[node + 1];
    const float* base = feat + (size_t)lane * 4;

    float4 a0 = {0.f, 0.f, 0.f, 0.f}, a1 = a0, a2 = a0, a3 = a0;
    int e = beg;
    for (; e + 4 <= end; e += 4) {
        int s0 = __ldg(&g_csr[e + 0]);
        int s1 = __ldg(&g_csr[e + 1]);
        int s2 = __ldg(&g_csr[e + 2]);
        int s3 = __ldg(&g_csr[e + 3]);
        float4 v0 = *(const float4*)(base + (size_t)s0 * F);
        float4 v1 = *(const float4*)(base + (size_t)s1 * F);
        float4 v2 = *(const float4*)(base + (size_t)s2 * F);
        float4 v3 = *(const float4*)(base + (size_t)s3 * F);
        a0.x += v0.x; a0.y += v0.y; a0.z += v0.z; a0.w += v0.w;
        a1.x += v1.x; a1.y += v1.y; a1.z += v1.z; a1.w += v1.w;
        a2.x += v2.x; a2.y += v2.y; a2.z += v2.z; a2.w += v2.w;
        a3.x += v3.x; a3.y += v3.y; a3.z += v3.z; a3.w += v3.w;
    }
    for (; e < end; e++) {
        int s0 = __ldg(&g_csr[e]);
        float4 v0 = *(const float4*)(base + (size_t)s0 * F);
        a0.x += v0.x; a0.y += v0.y; a0.z += v0.z; a0.w += v0.w;
    }
    a0.x += a1.x + a2.x + a3.x;
    a0.y += a1.y + a2.y + a3.y;
    a0.z += a1.z + a2.z + a3.z;
    a0.w += a1.w + a2.w + a3.w;

    int deg = end - beg;
    float inv = 1.0f / (float)max(deg, 1);
    a0.x *= inv; a0.y *= inv; a0.z *= inv; a0.w *= inv;
    *(float4*)(g_mean + (size_t)node * F + lane * 4) = a0;
}

// ---------------- fused dual GEMM: out = g_mean@Wl + A@Wr + b (opt relu) -----
// A input: use_gh_in ? g_h : Ax_g. Output: use_gh_out ? g_h : out_g.
// Block tile: 128 rows x 128 cols. 256 threads, 8x8 register blocking.
// Static shared 32 KB: Wl/Wr staged 16 k-rows at a time, A staged 16-wide.
__global__ __launch_bounds__(256) void k_gemm_dual(
    const float* __restrict__ Ax_g, int use_gh_in,
    const float* __restrict__ Wl_g, const float* __restrict__ Wr_g,
    const float* __restrict__ bias,
    float* __restrict__ out_g, int use_gh_out,
    int n, int do_relu)
{
    __shared__ float Wls[16 * 128];   // [k][col]
    __shared__ float Wrs[16 * 128];
    __shared__ float Ams[128 * 16];   // [row][k]
    __shared__ float Axs[128 * 16];

    const float* Ax  = use_gh_in  ? (const float*)g_h : Ax_g;
    float*       out = use_gh_out ? (float*)g_h       : out_g;

    int t = threadIdx.x;
    int row0 = blockIdx.x * 128;
    int tx = t & 15;    // col group: cols [tx*8, tx*8+8)
    int ty = t >> 4;    // row group: rows [ty*8, ty*8+8)

    float acc[8][8];
#pragma unroll
    for (int i = 0; i < 8; i++)
#pragma unroll
        for (int j = 0; j < 8; j++) acc[i][j] = 0.f;

    for (int kb = 0; kb < 8; kb++) {
        __syncthreads();
        // stage weights: 16 k-rows x 128 cols each = 512 float4 per matrix
        for (int i = t; i < 512; i += 256) {
            int row = i >> 5;       // 0..15
            int cg  = i & 31;       // col group of 4
            ((float4*)Wls)[i] = ((const float4*)(Wl_g + (size_t)(kb * 16 + row) * 128))[cg];
            ((float4*)Wrs)[i] = ((const float4*)(Wr_g + (size_t)(kb * 16 + row) * 128))[cg];
        }
        // stage A (mean + x): 128 rows x 16 k = 512 float4 per matrix
        for (int i = t; i < 512; i += 256) {
            int row = i >> 2;       // 0..127
            int c4  = i & 3;        // k group of 4
            int r = row0 + row;
            float4 vm = {0.f, 0.f, 0.f, 0.f};
            float4 vx = vm;
            if (r < n) {
                size_t gidx = (size_t)r * F + kb * 16 + c4 * 4;
                vm = *(const float4*)&g_mean[gidx];
                vx = *(const float4*)&Ax[gidx];
            }
            *(float4*)&Ams[row * 16 + c4 * 4] = vm;
            *(float4*)&Axs[row * 16 + c4 * 4] = vx;
        }
        __syncthreads();

#pragma unroll
        for (int kk = 0; kk < 16; kk++) {
            float wl[8], wr[8];
            *(float4*)&wl[0] = *(float4*)&Wls[kk * 128 + tx * 8];
            *(float4*)&wl[4] = *(float4*)&Wls[kk * 128 + tx * 8 + 4];
            *(float4*)&wr[0] = *(float4*)&Wrs[kk * 128 + tx * 8];
            *(float4*)&wr[4] = *(float4*)&Wrs[kk * 128 + tx * 8 + 4];
#pragma unroll
            for (int rr = 0; rr < 8; rr++) {
                float am = Ams[(ty * 8 + rr) * 16 + kk];
                float ax = Axs[(ty * 8 + rr) * 16 + kk];
#pragma unroll
                for (int cc = 0; cc < 8; cc++)
                    acc[rr][cc] += am * wl[cc] + ax * wr[cc];
            }
        }
    }

    // epilogue
    float bv[8];
    *(float4*)&bv[0] = *(const float4*)&bias[tx * 8];
    *(float4*)&bv[4] = *(const float4*)&bias[tx * 8 + 4];
#pragma unroll
    for (int rr = 0; rr < 8; rr++) {
        int r = row0 + ty * 8 + rr;
        if (r >= n) continue;
        float o[8];
#pragma unroll
        for (int cc = 0; cc < 8; cc++) {
            float v = acc[rr][cc] + bv[cc];
            if (do_relu) v = fmaxf(v, 0.f);
            o[cc] = v;
        }
        *(float4*)&out[(size_t)r * F + tx * 8]     = *(float4*)&o[0];
        *(float4*)&out[(size_t)r * F + tx * 8 + 4] = *(float4*)&o[4];
    }
}

// ---------------- launch: kernel launches ONLY -------------------------------
extern "C" void kernel_launch(void* const* d_in, const int* in_sizes, int n_in,
                              void* d_out, int out_size) {
    const float* x   = (const float*)d_in[0];
    const int*   ei  = (const int*)d_in[1];   // int32 [2, E] (JAX x64 disabled)
    const float* Wl1 = (const float*)d_in[2];
    const float* Wr1 = (const float*)d_in[3];
    const float* b1  = (const float*)d_in[4];
    const float* Wl2 = (const float*)d_in[5];
    const float* Wr2 = (const float*)d_in[6];
    const float* b2  = (const float*)d_in[7];
    float* out = (float*)d_out;

    int n = in_sizes[0] / F;
    int E = in_sizes[1] / 2;
    if (n > MAXN) n = MAXN;
    if (E > MAXE) E = MAXE;

    const int* src = ei;
    const int* dst = ei + E;

    // 1) CSR build by dst
    k_zero_cnt<<<(n + 255) / 256, 256>>>(n);
    k_hist<<<(E + 255) / 256, 256>>>(dst, E, n);
    k_scan<<<1, 1024>>>(n);
    k_scatter<<<(E + 255) / 256, 256>>>(src, dst, E, n);

    int agg_grid  = (n + 7) / 8;
    int gemm_grid = (n + 127) / 128;

    // 2) layer 1: mean-agg(x) -> g_mean; g_h = relu(g_mean@Wl1 + x@Wr1 + b1)
    k_agg<<<agg_grid, 256>>>(x, 0, n);
    k_gemm_dual<<<gemm_grid, 256>>>(x, 0, Wl1, Wr1, b1, nullptr, 1, n, 1);

    // 3) layer 2: mean-agg(g_h) -> g_mean; out = g_mean@Wl2 + g_h@Wr2 + b2
    k_agg<<<agg_grid, 256>>>(nullptr, 1, n);
    k_gemm_dual<<<gemm_grid, 256>>>(nullptr, 1, Wl2, Wr2, b2, out, 0, n, 0);
}

// round 9
// speedup vs baseline: 2.1935x; 2.1935x over previous
#include <cuda_runtime.h>
#include <cuda_bf16.h>
#include <cstdint>

#define MAXN 100000
#define MAXE 1600000
#define F 128

// ---------------- scratch (static device globals; no allocs allowed) ----------
__device__ int   g_cnt[MAXN];
__device__ int   g_off[MAXN + 1];
__device__ int   g_cur[MAXN];
__device__ int   g_csr[MAXE];
__device__ int   g_blk[512];
__device__ int   g_blkoff[512];
__device__ float g_mean[(size_t)MAXN * F];   // aggregated means
__device__ float g_h[(size_t)MAXN * F];      // layer-1 activations
__device__ float g_wt[128 * 256];            // g_wt[n][k] = tf32(concat(Wl,Wr)[k][n])

// ---------------- helpers ----------------------------------------------------
__device__ __forceinline__ uint32_t f2tf32(float x) {
    uint32_t o;
    asm("cvt.rna.tf32.f32 %0, %1;" : "=r"(o) : "f"(x));
    return o;
}
__device__ __forceinline__ void mma_tf32(float* c, const uint32_t* a, const uint32_t* b) {
    asm volatile(
        "mma.sync.aligned.m16n8k8.row.col.f32.tf32.tf32.f32 "
        "{%0,%1,%2,%3}, {%4,%5,%6,%7}, {%8,%9}, {%0,%1,%2,%3};"
        : "+f"(c[0]), "+f"(c[1]), "+f"(c[2]), "+f"(c[3])
        : "r"(a[0]), "r"(a[1]), "r"(a[2]), "r"(a[3]), "r"(b[0]), "r"(b[1]));
}

// ---------------- CSR build --------------------------------------------------
__global__ void k_zero_cnt(int n) {
    int i = blockIdx.x * 256 + threadIdx.x;
    if (i < n) g_cnt[i] = 0;
}

__global__ void k_hist(const int* __restrict__ dst, int E, int n) {
    int e = blockIdx.x * 256 + threadIdx.x;
    if (e < E) {
        int d = dst[e];
        if ((unsigned)d < (unsigned)n) atomicAdd(&g_cnt[d], 1);
    }
}

__global__ void k_blksum(int n) {
    __shared__ int sh[256];
    int b = blockIdx.x, t = threadIdx.x;
    int i = b * 256 + t;
    sh[t] = (i < n) ? g_cnt[i] : 0;
    __syncthreads();
    for (int s = 128; s > 0; s >>= 1) {
        if (t < s) sh[t] += sh[t + s];
        __syncthreads();
    }
    if (t == 0) g_blk[b] = sh[0];
}

__global__ void k_blkscan(int nb, int n) {
    __shared__ int sh[512];
    int t = threadIdx.x;
    int v = (t < nb) ? g_blk[t] : 0;
    sh[t] = v;
    __syncthreads();
    for (int d = 1; d < 512; d <<= 1) {
        int u = (t >= d) ? sh[t - d] : 0;
        __syncthreads();
        sh[t] += u;
        __syncthreads();
    }
    g_blkoff[t] = sh[t] - v;
    if (t == 511) g_off[n] = sh[511];
}

__global__ void k_scanout(int n) {
    __shared__ int sh[256];
    int b = blockIdx.x, t = threadIdx.x;
    int i = b * 256 + t;
    int c = (i < n) ? g_cnt[i] : 0;
    sh[t] = c;
    __syncthreads();
    for (int d = 1; d < 256; d <<= 1) {
        int u = (t >= d) ? sh[t - d] : 0;
        __syncthreads();
        sh[t] += u;
        __syncthreads();
    }
    if (i < n) {
        g_off[i] = g_blkoff[b] + sh[t] - c;
        g_cur[i] = 0;
    }
}

__global__ void k_scatter(const int* __restrict__ src,
                          const int* __restrict__ dst, int E, int n) {
    int e = blockIdx.x * 256 + threadIdx.x;
    if (e < E) {
        int d = dst[e];
        int s = src[e];
        if ((unsigned)d < (unsigned)n && (unsigned)s < (unsigned)n) {
            int p = g_off[d] + atomicAdd(&g_cur[d], 1);
            g_csr[p] = s;
        }
    }
}

// ---------------- mean aggregation (CSR, no atomics) -------------------------
__global__ void k_agg(const float* __restrict__ feat_in, int use_gh, int n) {
    int node = blockIdx.x * 8 + (threadIdx.x >> 5);
    int lane = threadIdx.x & 31;
    if (node >= n) return;
    const float* feat = use_gh ? (const float*)g_h : feat_in;
    int beg = g_off[node];
    int end = g_off[node + 1];
    const float* base = feat + (size_t)lane * 4;

    float4 a0 = {0.f, 0.f, 0.f, 0.f}, a1 = a0, a2 = a0, a3 = a0;
    int e = beg;
    for (; e + 4 <= end; e += 4) {
        int s0 = __ldg(&g_csr[e + 0]);
        int s1 = __ldg(&g_csr[e + 1]);
        int s2 = __ldg(&g_csr[e + 2]);
        int s3 = __ldg(&g_csr[e + 3]);
        float4 v0 = *(const float4*)(base + (size_t)s0 * F);
        float4 v1 = *(const float4*)(base + (size_t)s1 * F);
        float4 v2 = *(const float4*)(base + (size_t)s2 * F);
        float4 v3 = *(const float4*)(base + (size_t)s3 * F);
        a0.x += v0.x; a0.y += v0.y; a0.z += v0.z; a0.w += v0.w;
        a1.x += v1.x; a1.y += v1.y; a1.z += v1.z; a1.w += v1.w;
        a2.x += v2.x; a2.y += v2.y; a2.z += v2.z; a2.w += v2.w;
        a3.x += v3.x; a3.y += v3.y; a3.z += v3.z; a3.w += v3.w;
    }
    for (; e < end; e++) {
        int s0 = __ldg(&g_csr[e]);
        float4 v0 = *(const float4*)(base + (size_t)s0 * F);
        a0.x += v0.x; a0.y += v0.y; a0.z += v0.z; a0.w += v0.w;
    }
    a0.x += a1.x + a2.x + a3.x;
    a0.y += a1.y + a2.y + a3.y;
    a0.z += a1.z + a2.z + a3.z;
    a0.w += a1.w + a2.w + a3.w;

    int deg = end - beg;
    float inv = 1.0f / (float)max(deg, 1);
    a0.x *= inv; a0.y *= inv; a0.z *= inv; a0.w *= inv;
    *(float4*)(g_mean + (size_t)node * F + lane * 4) = a0;
}

// ---------------- weight prep: g_wt[n][k] = tf32(concat(Wl,Wr)[k][n]) --------
__global__ void k_prep(const float* __restrict__ Wl, const float* __restrict__ Wr) {
    int idx = blockIdx.x * 256 + threadIdx.x;   // 32768 total
    if (idx >= 128 * 256) return;
    int nn = idx >> 8;          // 0..127 (output col)
    int k  = idx & 255;         // 0..255
    float v = (k < 128) ? Wl[k * 128 + nn] : Wr[(k - 128) * 128 + nn];
    ((uint32_t*)g_wt)[nn * 256 + k] = f2tf32(v);
}

// ---------------- tf32 mma.sync dual GEMM ------------------------------------
// D[128r][128c] = [mean | A](K=256) @ g_wt^T, + bias, optional relu.
// 8 warps (4 m-groups x 2 n-groups), each warp 32x64 via m16n8k8 atoms.
__global__ __launch_bounds__(256) void k_gemm_mma(
    const float* __restrict__ Ax_g, int use_gh_in,
    const float* __restrict__ bias,
    float* __restrict__ out_g, int use_gh_out,
    int n, int do_relu)
{
    __shared__ uint32_t sA[128][33];   // [row][k], padded
    __shared__ uint32_t sB[128][33];   // [n][k], padded
    __shared__ float sBias[128];

    const float* Ax  = use_gh_in  ? (const float*)g_h : Ax_g;
    float*       out = use_gh_out ? (float*)g_h       : out_g;

    int t = threadIdx.x;
    int warp = t >> 5;
    int lane = t & 31;
    int warp_m = warp & 3;          // rows warp_m*32
    int warp_n = warp >> 2;         // cols warp_n*64
    int group = lane >> 2;          // 0..7
    int tig = lane & 3;             // 0..3
    int row0 = blockIdx.x * 128;

    if (t < 128) sBias[t] = bias[t];

    float acc[2][8][4];
#pragma unroll
    for (int i = 0; i < 2; i++)
#pragma unroll
        for (int j = 0; j < 8; j++)
#pragma unroll
            for (int q = 0; q < 4; q++) acc[i][j][q] = 0.f;

    for (int ch = 0; ch < 8; ch++) {
        const float* srcp = (ch < 4) ? (const float*)g_mean : Ax;
        int kcol = (ch & 3) * 32;
        __syncthreads();
        // stage A: 128 rows x 32 k (fp32 -> tf32)
#pragma unroll
        for (int it = 0; it < 4; it++) {
            int i = t + it * 256;        // 0..1023 float4 slots
            int row = i >> 3;
            int c4 = (i & 7) * 4;
            int r = row0 + row;
            float4 v = make_float4(0.f, 0.f, 0.f, 0.f);
            if (r < n) v = *(const float4*)&srcp[(size_t)r * F + kcol + c4];
            sA[row][c4 + 0] = f2tf32(v.x);
            sA[row][c4 + 1] = f2tf32(v.y);
            sA[row][c4 + 2] = f2tf32(v.z);
            sA[row][c4 + 3] = f2tf32(v.w);
        }
        // stage B: 128 n x 32 k from g_wt (already tf32 bits)
#pragma unroll
        for (int it = 0; it < 4; it++) {
            int i = t + it * 256;
            int row = i >> 3;
            int c4 = (i & 7) * 4;
            uint4 u = *(const uint4*)&((const uint32_t*)g_wt)[row * 256 + ch * 32 + c4];
            sB[row][c4 + 0] = u.x;
            sB[row][c4 + 1] = u.y;
            sB[row][c4 + 2] = u.z;
            sB[row][c4 + 3] = u.w;
        }
        __syncthreads();

#pragma unroll
        for (int ks = 0; ks < 4; ks++) {
            int kk = ks * 8;
            uint32_t a[2][4];
#pragma unroll
            for (int mf = 0; mf < 2; mf++) {
                int mrow = warp_m * 32 + mf * 16;
                a[mf][0] = sA[mrow + group][kk + tig];
                a[mf][1] = sA[mrow + group + 8][kk + tig];
                a[mf][2] = sA[mrow + group][kk + tig + 4];
                a[mf][3] = sA[mrow + group + 8][kk + tig + 4];
            }
            uint32_t b[8][2];
#pragma unroll
            for (int nf = 0; nf < 8; nf++) {
                int ncol = warp_n * 64 + nf * 8 + group;
                b[nf][0] = sB[ncol][kk + tig];
                b[nf][1] = sB[ncol][kk + tig + 4];
            }
#pragma unroll
            for (int mf = 0; mf < 2; mf++)
#pragma unroll
                for (int nf = 0; nf < 8; nf++)
                    mma_tf32(acc[mf][nf], a[mf], b[nf]);
        }
    }

    // epilogue: c0/c1 -> (row=g, col=2*tig(+1)); c2/c3 -> (row=g+8)
#pragma unroll
    for (int mf = 0; mf < 2; mf++) {
        int r_lo = row0 + warp_m * 32 + mf * 16 + group;
        int r_hi = r_lo + 8;
#pragma unroll
        for (int nf = 0; nf < 8; nf++) {
            int cc = warp_n * 64 + nf * 8 + tig * 2;
            float2 lo, hi;
            lo.x = acc[mf][nf][0] + sBias[cc];
            lo.y = acc[mf][nf][1] + sBias[cc + 1];
            hi.x = acc[mf][nf][2] + sBias[cc];
            hi.y = acc[mf][nf][3] + sBias[cc + 1];
            if (do_relu) {
                lo.x = fmaxf(lo.x, 0.f); lo.y = fmaxf(lo.y, 0.f);
                hi.x = fmaxf(hi.x, 0.f); hi.y = fmaxf(hi.y, 0.f);
            }
            if (r_lo < n) *(float2*)&out[(size_t)r_lo * F + cc] = lo;
            if (r_hi < n) *(float2*)&out[(size_t)r_hi * F + cc] = hi;
        }
    }
}

// ---------------- launch: kernel launches ONLY -------------------------------
extern "C" void kernel_launch(void* const* d_in, const int* in_sizes, int n_in,
                              void* d_out, int out_size) {
    const float* x   = (const float*)d_in[0];
    const int*   ei  = (const int*)d_in[1];   // int32 [2, E]
    const float* Wl1 = (const float*)d_in[2];
    const float* Wr1 = (const float*)d_in[3];
    const float* b1  = (const float*)d_in[4];
    const float* Wl2 = (const float*)d_in[5];
    const float* Wr2 = (const float*)d_in[6];
    const float* b2  = (const float*)d_in[7];
    float* out = (float*)d_out;

    int n = in_sizes[0] / F;
    int E = in_sizes[1] / 2;
    if (n > MAXN) n = MAXN;
    if (E > MAXE) E = MAXE;

    const int* src = ei;
    const int* dst = ei + E;

    int nb = (n + 255) / 256;

    // 1) CSR build by dst
    k_zero_cnt<<<nb, 256>>>(n);
    k_hist<<<(E + 255) / 256, 256>>>(dst, E, n);
    k_blksum<<<nb, 256>>>(n);
    k_blkscan<<<1, 512>>>(nb, n);
    k_scanout<<<nb, 256>>>(n);
    k_scatter<<<(E + 255) / 256, 256>>>(src, dst, E, n);

    int agg_grid  = (n + 7) / 8;
    int gemm_grid = (n + 127) / 128;

    // 2) layer 1
    k_agg<<<agg_grid, 256>>>(x, 0, n);
    k_prep<<<128, 256>>>(Wl1, Wr1);
    k_gemm_mma<<<gemm_grid, 256>>>(x, 0, b1, nullptr, 1, n, 1);

    // 3) layer 2
    k_agg<<<agg_grid, 256>>>(nullptr, 1, n);
    k_prep<<<128, 256>>>(Wl2, Wr2);
    k_gemm_mma<<<gemm_grid, 256>>>(nullptr, 1, b2, out, 0, n, 0);
}

// round 10
// speedup vs baseline: 3.5217x; 1.6055x over previous
#include <cuda_runtime.h>
#include <cuda_fp16.h>
#include <cstdint>

#define MAXN 100000
#define MAXE 1600000
#define F 128

// ---------------- scratch (static device globals; no allocs allowed) ----------
__device__ int    g_cnt[MAXN];
__device__ int    g_off[MAXN + 1];
__device__ int    g_cur[MAXN];
__device__ int    g_csr[MAXE];
__device__ int    g_blk[512];
__device__ int    g_blkoff[512];
__device__ __half g_xh[(size_t)MAXN * F];     // fp16 copy of x
__device__ __half g_hh[(size_t)MAXN * F];     // fp16 layer-1 activations
__device__ __half g_meanh[(size_t)MAXN * F];  // fp16 aggregated means
__device__ __half g_wth[128 * 256];           // g_wth[n][k] = fp16(concat(Wl,Wr)[k][n])

// ---------------- helpers ----------------------------------------------------
__device__ __forceinline__ void mma_f16(float* c, const uint32_t* a, const uint32_t* b) {
    asm volatile(
        "mma.sync.aligned.m16n8k16.row.col.f32.f16.f16.f32 "
        "{%0,%1,%2,%3}, {%4,%5,%6,%7}, {%8,%9}, {%0,%1,%2,%3};"
        : "+f"(c[0]), "+f"(c[1]), "+f"(c[2]), "+f"(c[3])
        : "r"(a[0]), "r"(a[1]), "r"(a[2]), "r"(a[3]), "r"(b[0]), "r"(b[1]));
}

// ---------------- CSR build --------------------------------------------------
__global__ void k_zero_cnt(int n) {
    int i = blockIdx.x * 256 + threadIdx.x;
    if (i < n) g_cnt[i] = 0;
}

__global__ void k_hist(const int* __restrict__ dst, int E, int n) {
    int e = blockIdx.x * 256 + threadIdx.x;
    if (e < E) {
        int d = dst[e];
        if ((unsigned)d < (unsigned)n) atomicAdd(&g_cnt[d], 1);
    }
}

__global__ void k_blksum(int n) {
    __shared__ int sh[256];
    int b = blockIdx.x, t = threadIdx.x;
    int i = b * 256 + t;
    sh[t] = (i < n) ? g_cnt[i] : 0;
    __syncthreads();
    for (int s = 128; s > 0; s >>= 1) {
        if (t < s) sh[t] += sh[t + s];
        __syncthreads();
    }
    if (t == 0) g_blk[b] = sh[0];
}

__global__ void k_blkscan(int nb, int n) {
    __shared__ int sh[512];
    int t = threadIdx.x;
    int v = (t < nb) ? g_blk[t] : 0;
    sh[t] = v;
    __syncthreads();
    for (int d = 1; d < 512; d <<= 1) {
        int u = (t >= d) ? sh[t - d] : 0;
        __syncthreads();
        sh[t] += u;
        __syncthreads();
    }
    g_blkoff[t] = sh[t] - v;
    if (t == 511) g_off[n] = sh[511];
}

__global__ void k_scanout(int n) {
    __shared__ int sh[256];
    int b = blockIdx.x, t = threadIdx.x;
    int i = b * 256 + t;
    int c = (i < n) ? g_cnt[i] : 0;
    sh[t] = c;
    __syncthreads();
    for (int d = 1; d < 256; d <<= 1) {
        int u = (t >= d) ? sh[t - d] : 0;
        __syncthreads();
        sh[t] += u;
        __syncthreads();
    }
    if (i < n) {
        g_off[i] = g_blkoff[b] + sh[t] - c;
        g_cur[i] = 0;
    }
}

__global__ void k_scatter(const int* __restrict__ src,
                          const int* __restrict__ dst, int E, int n) {
    int e = blockIdx.x * 256 + threadIdx.x;
    if (e < E) {
        int d = dst[e];
        int s = src[e];
        if ((unsigned)d < (unsigned)n && (unsigned)s < (unsigned)n) {
            int p = g_off[d] + atomicAdd(&g_cur[d], 1);
            g_csr[p] = s;
        }
    }
}

// ---------------- x -> fp16 conversion ---------------------------------------
__global__ void k_x2h(const float* __restrict__ x, int n) {
    int i = blockIdx.x * 256 + threadIdx.x;   // one float4 -> 4 halves
    if (i < n * 32) {
        float4 v = ((const float4*)x)[i];
        __half2 lo = __floats2half2_rn(v.x, v.y);
        __half2 hi = __floats2half2_rn(v.z, v.w);
        uint2 u;
        u.x = *(uint32_t*)&lo;
        u.y = *(uint32_t*)&hi;
        ((uint2*)g_xh)[i] = u;
    }
}

// ---------------- mean aggregation (CSR, fp16 gather, fp32 accumulate) -------
// 8 nodes per 256-thread block; 32 lanes per node; each lane owns 4 channels.
__global__ void k_agg(int use_gh, int n) {
    int node = blockIdx.x * 8 + (threadIdx.x >> 5);
    int lane = threadIdx.x & 31;
    if (node >= n) return;
    const __half* feat = use_gh ? g_hh : g_xh;
    int beg = g_off[node];
    int end = g_off[node + 1];
    const __half* base = feat + (size_t)lane * 4;

    float4 a0 = {0.f, 0.f, 0.f, 0.f}, a1 = a0, a2 = a0, a3 = a0;
    int e = beg;
    for (; e + 4 <= end; e += 4) {
        int s0 = __ldg(&g_csr[e + 0]);
        int s1 = __ldg(&g_csr[e + 1]);
        int s2 = __ldg(&g_csr[e + 2]);
        int s3 = __ldg(&g_csr[e + 3]);
        uint2 u0 = *(const uint2*)(base + (size_t)s0 * F);
        uint2 u1 = *(const uint2*)(base + (size_t)s1 * F);
        uint2 u2 = *(const uint2*)(base + (size_t)s2 * F);
        uint2 u3 = *(const uint2*)(base + (size_t)s3 * F);
        float2 p, q;
        p = __half22float2(*(__half2*)&u0.x); q = __half22float2(*(__half2*)&u0.y);
        a0.x += p.x; a0.y += p.y; a0.z += q.x; a0.w += q.y;
        p = __half22float2(*(__half2*)&u1.x); q = __half22float2(*(__half2*)&u1.y);
        a1.x += p.x; a1.y += p.y; a1.z += q.x; a1.w += q.y;
        p = __half22float2(*(__half2*)&u2.x); q = __half22float2(*(__half2*)&u2.y);
        a2.x += p.x; a2.y += p.y; a2.z += q.x; a2.w += q.y;
        p = __half22float2(*(__half2*)&u3.x); q = __half22float2(*(__half2*)&u3.y);
        a3.x += p.x; a3.y += p.y; a3.z += q.x; a3.w += q.y;
    }
    for (; e < end; e++) {
        int s0 = __ldg(&g_csr[e]);
        uint2 u0 = *(const uint2*)(base + (size_t)s0 * F);
        float2 p = __half22float2(*(__half2*)&u0.x);
        float2 q = __half22float2(*(__half2*)&u0.y);
        a0.x += p.x; a0.y += p.y; a0.z += q.x; a0.w += q.y;
    }
    a0.x += a1.x + a2.x + a3.x;
    a0.y += a1.y + a2.y + a3.y;
    a0.z += a1.z + a2.z + a3.z;
    a0.w += a1.w + a2.w + a3.w;

    int deg = end - beg;
    float inv = 1.0f / (float)max(deg, 1);
    __half2 lo = __floats2half2_rn(a0.x * inv, a0.y * inv);
    __half2 hi = __floats2half2_rn(a0.z * inv, a0.w * inv);
    uint2 u;
    u.x = *(uint32_t*)&lo;
    u.y = *(uint32_t*)&hi;
    *(uint2*)(g_meanh + (size_t)node * F + lane * 4) = u;
}

// ---------------- weight prep: g_wth[n][k] = fp16(concat(Wl,Wr)[k][n]) -------
__global__ void k_prep(const float* __restrict__ Wl, const float* __restrict__ Wr) {
    int idx = blockIdx.x * 256 + threadIdx.x;   // 32768 total
    if (idx >= 128 * 256) return;
    int nn = idx >> 8;          // 0..127 (output col)
    int k  = idx & 255;         // 0..255
    float v = (k < 128) ? Wl[k * 128 + nn] : Wr[(k - 128) * 128 + nn];
    g_wth[nn * 256 + k] = __float2half_rn(v);
}

// ---------------- fp16 mma.sync dual GEMM ------------------------------------
// D[128r][128c] = [mean | self](K=256, fp16) @ g_wth^T, fp32 acc, + bias, relu.
// 8 warps (4 m x 2 n), each warp 32x64 via m16n8k16 atoms.
__global__ __launch_bounds__(256) void k_gemm_mma(
    const float* __restrict__ bias,
    float* __restrict__ out_g, int use_gh_in, int out_is_half,
    int n, int do_relu)
{
    __shared__ uint32_t sA[128][20];   // 16 used + pad (80B row stride, 16B-aligned)
    __shared__ uint32_t sB[128][20];
    __shared__ float sBias[128];

    const __half* selfp = use_gh_in ? g_hh : g_xh;

    int t = threadIdx.x;
    int warp = t >> 5;
    int lane = t & 31;
    int warp_m = warp & 3;          // rows warp_m*32
    int warp_n = warp >> 2;         // cols warp_n*64
    int group = lane >> 2;          // 0..7
    int tig = lane & 3;             // 0..3
    int row0 = blockIdx.x * 128;

    if (t < 128) sBias[t] = bias[t];

    float acc[2][8][4];
#pragma unroll
    for (int i = 0; i < 2; i++)
#pragma unroll
        for (int j = 0; j < 8; j++)
#pragma unroll
            for (int q = 0; q < 4; q++) acc[i][j][q] = 0.f;

    for (int ch = 0; ch < 8; ch++) {
        const __half* srcp = (ch < 4) ? g_meanh : selfp;
        int kcol = (ch & 3) * 32;
        __syncthreads();
        // stage A: 128 rows x 32 halves (one uint4 = 8 halves, 4 per row)
#pragma unroll
        for (int it = 0; it < 2; it++) {
            int i = t + it * 256;        // 0..511
            int row = i >> 2;
            int c4 = i & 3;
            int r = row0 + row;
            uint4 u = make_uint4(0u, 0u, 0u, 0u);
            if (r < n) u = *(const uint4*)&srcp[(size_t)r * F + kcol + c4 * 8];
            *(uint4*)&sA[row][c4 * 4] = u;
        }
        // stage B: 128 n x 32 halves from g_wth
#pragma unroll
        for (int it = 0; it < 2; it++) {
            int i = t + it * 256;
            int row = i >> 2;
            int c4 = i & 3;
            uint4 u = *(const uint4*)&g_wth[row * 256 + ch * 32 + c4 * 8];
            *(uint4*)&sB[row][c4 * 4] = u;
        }
        __syncthreads();

#pragma unroll
        for (int ks = 0; ks < 2; ks++) {
            uint32_t a[2][4];
#pragma unroll
            for (int mf = 0; mf < 2; mf++) {
                int mrow = warp_m * 32 + mf * 16;
                a[mf][0] = sA[mrow + group][ks * 8 + tig];
                a[mf][1] = sA[mrow + group + 8][ks * 8 + tig];
                a[mf][2] = sA[mrow + group][ks * 8 + tig + 4];
                a[mf][3] = sA[mrow + group + 8][ks * 8 + tig + 4];
            }
            uint32_t b[8][2];
#pragma unroll
            for (int nf = 0; nf < 8; nf++) {
                int ncol = warp_n * 64 + nf * 8 + group;
                b[nf][0] = sB[ncol][ks * 8 + tig];
                b[nf][1] = sB[ncol][ks * 8 + tig + 4];
            }
#pragma unroll
            for (int mf = 0; mf < 2; mf++)
#pragma unroll
                for (int nf = 0; nf < 8; nf++)
                    mma_f16(acc[mf][nf], a[mf], b[nf]);
        }
    }

    // epilogue: c0/c1 -> (row=g, cols 2t,2t+1); c2/c3 -> (row=g+8)
#pragma unroll
    for (int mf = 0; mf < 2; mf++) {
        int r_lo = row0 + warp_m * 32 + mf * 16 + group;
        int r_hi = r_lo + 8;
#pragma unroll
        for (int nf = 0; nf < 8; nf++) {
            int cc = warp_n * 64 + nf * 8 + tig * 2;
            float2 lo, hi;
            lo.x = acc[mf][nf][0] + sBias[cc];
            lo.y = acc[mf][nf][1] + sBias[cc + 1];
            hi.x = acc[mf][nf][2] + sBias[cc];
            hi.y = acc[mf][nf][3] + sBias[cc + 1];
            if (do_relu) {
                lo.x = fmaxf(lo.x, 0.f); lo.y = fmaxf(lo.y, 0.f);
                hi.x = fmaxf(hi.x, 0.f); hi.y = fmaxf(hi.y, 0.f);
            }
            if (out_is_half) {
                __half2 l2 = __floats2half2_rn(lo.x, lo.y);
                __half2 h2 = __floats2half2_rn(hi.x, hi.y);
                if (r_lo < n) *(__half2*)&g_hh[(size_t)r_lo * F + cc] = l2;
                if (r_hi < n) *(__half2*)&g_hh[(size_t)r_hi * F + cc] = h2;
            } else {
                if (r_lo < n) *(float2*)&out_g[(size_t)r_lo * F + cc] = lo;
                if (r_hi < n) *(float2*)&out_g[(size_t)r_hi * F + cc] = hi;
            }
        }
    }
}

// ---------------- launch: kernel launches ONLY -------------------------------
extern "C" void kernel_launch(void* const* d_in, const int* in_sizes, int n_in,
                              void* d_out, int out_size) {
    const float* x   = (const float*)d_in[0];
    const int*   ei  = (const int*)d_in[1];   // int32 [2, E]
    const float* Wl1 = (const float*)d_in[2];
    const float* Wr1 = (const float*)d_in[3];
    const float* b1  = (const float*)d_in[4];
    const float* Wl2 = (const float*)d_in[5];
    const float* Wr2 = (const float*)d_in[6];
    const float* b2  = (const float*)d_in[7];
    float* out = (float*)d_out;

    int n = in_sizes[0] / F;
    int E = in_sizes[1] / 2;
    if (n > MAXN) n = MAXN;
    if (E > MAXE) E = MAXE;

    const int* src = ei;
    const int* dst = ei + E;

    int nb = (n + 255) / 256;

    // 1) CSR build by dst (+ x->fp16 conversion overlapped in the stream)
    k_zero_cnt<<<nb, 256>>>(n);
    k_hist<<<(E + 255) / 256, 256>>>(dst, E, n);
    k_x2h<<<(n * 32 + 255) / 256, 256>>>(x, n);
    k_blksum<<<nb, 256>>>(n);
    k_blkscan<<<1, 512>>>(nb, n);
    k_scanout<<<nb, 256>>>(n);
    k_scatter<<<(E + 255) / 256, 256>>>(src, dst, E, n);

    int agg_grid  = (n + 7) / 8;
    int gemm_grid = (n + 127) / 128;

    // 2) layer 1: agg(x_h) -> mean_h; g_hh = relu(...)
    k_agg<<<agg_grid, 256>>>(0, n);
    k_prep<<<128, 256>>>(Wl1, Wr1);
    k_gemm_mma<<<gemm_grid, 256>>>(b1, nullptr, 0, 1, n, 1);

    // 3) layer 2: agg(h_h) -> mean_h; out = ...
    k_agg<<<agg_grid, 256>>>(1, n);
    k_prep<<<128, 256>>>(Wl2, Wr2);
    k_gemm_mma<<<gemm_grid, 256>>>(b2, out, 1, 0, n, 0);
}

// round 11
// speedup vs baseline: 4.0723x; 1.1563x over previous
#include <cuda_runtime.h>
#include <cuda_fp16.h>
#include <cstdint>

#define MAXN 100000
#define MAXE 1600000
#define F 128

// ---------------- scratch (static device globals; no allocs allowed) ----------
__device__ int    g_cnt[MAXN];
__device__ int    g_off[MAXN + 1];
__device__ int    g_cur[MAXN];
__device__ int    g_csr[MAXE];
__device__ int    g_blk[512];
__device__ int    g_blkoff[512];
__device__ __half g_xh[(size_t)MAXN * F];      // fp16 copy of x
__device__ __half g_hh[(size_t)MAXN * F];      // fp16 layer-1 activations
__device__ __half g_meanh[(size_t)MAXN * F];   // fp16 aggregated means
__device__ __half g_wth[2][128 * 256];         // per-layer [n][k] = fp16(concat(Wl,Wr)[k][n])

// ---------------- helpers ----------------------------------------------------
__device__ __forceinline__ void mma_f16(float* c, const uint32_t* a, const uint32_t* b) {
    asm volatile(
        "mma.sync.aligned.m16n8k16.row.col.f32.f16.f16.f32 "
        "{%0,%1,%2,%3}, {%4,%5,%6,%7}, {%8,%9}, {%0,%1,%2,%3};"
        : "+f"(c[0]), "+f"(c[1]), "+f"(c[2]), "+f"(c[3])
        : "r"(a[0]), "r"(a[1]), "r"(a[2]), "r"(a[3]), "r"(b[0]), "r"(b[1]));
}
__device__ __forceinline__ void ldsm4(uint32_t* r, uint32_t addr) {
    asm volatile("ldmatrix.sync.aligned.m8n8.x4.shared.b16 {%0,%1,%2,%3}, [%4];"
                 : "=r"(r[0]), "=r"(r[1]), "=r"(r[2]), "=r"(r[3]) : "r"(addr));
}
__device__ __forceinline__ uint32_t saddr(const void* p) {
    return (uint32_t)__cvta_generic_to_shared(p);
}
__device__ __forceinline__ void cp16(uint32_t dst, const void* src, int src_bytes) {
    asm volatile("cp.async.ca.shared.global [%0], [%1], 16, %2;"
                 :: "r"(dst), "l"(src), "r"(src_bytes) : "memory");
}
__device__ __forceinline__ void cp_commit() {
    asm volatile("cp.async.commit_group;" ::: "memory");
}
__device__ __forceinline__ void cp_wait0() {
    asm volatile("cp.async.wait_group 0;" ::: "memory");
}

// ---------------- init: zero counts + x -> fp16 -------------------------------
__global__ void k_init(const float* __restrict__ x, int n) {
    int i = blockIdx.x * 256 + threadIdx.x;
    if (i < n) g_cnt[i] = 0;
    if (i < n * 32) {
        float4 v = ((const float4*)x)[i];
        __half2 lo = __floats2half2_rn(v.x, v.y);
        __half2 hi = __floats2half2_rn(v.z, v.w);
        uint2 u;
        u.x = *(uint32_t*)&lo;
        u.y = *(uint32_t*)&hi;
        ((uint2*)g_xh)[i] = u;
    }
}

__global__ void k_hist(const int* __restrict__ dst, int E, int n) {
    int e = blockIdx.x * 256 + threadIdx.x;
    if (e < E) {
        int d = dst[e];
        if ((unsigned)d < (unsigned)n) atomicAdd(&g_cnt[d], 1);
    }
}

__global__ void k_blksum(int n) {
    __shared__ int sh[256];
    int b = blockIdx.x, t = threadIdx.x;
    int i = b * 256 + t;
    sh[t] = (i < n) ? g_cnt[i] : 0;
    __syncthreads();
    for (int s = 128; s > 0; s >>= 1) {
        if (t < s) sh[t] += sh[t + s];
        __syncthreads();
    }
    if (t == 0) g_blk[b] = sh[0];
}

__global__ void k_blkscan(int nb, int n) {
    __shared__ int sh[512];
    int t = threadIdx.x;
    int v = (t < nb) ? g_blk[t] : 0;
    sh[t] = v;
    __syncthreads();
    for (int d = 1; d < 512; d <<= 1) {
        int u = (t >= d) ? sh[t - d] : 0;
        __syncthreads();
        sh[t] += u;
        __syncthreads();
    }
    g_blkoff[t] = sh[t] - v;
    if (t == 511) g_off[n] = sh[511];
}

__global__ void k_scanout(int n) {
    __shared__ int sh[256];
    int b = blockIdx.x, t = threadIdx.x;
    int i = b * 256 + t;
    int c = (i < n) ? g_cnt[i] : 0;
    sh[t] = c;
    __syncthreads();
    for (int d = 1; d < 256; d <<= 1) {
        int u = (t >= d) ? sh[t - d] : 0;
        __syncthreads();
        sh[t] += u;
        __syncthreads();
    }
    if (i < n) {
        g_off[i] = g_blkoff[b] + sh[t] - c;
        g_cur[i] = 0;
    }
}

__global__ void k_scatter(const int* __restrict__ src,
                          const int* __restrict__ dst, int E, int n) {
    int e = blockIdx.x * 256 + threadIdx.x;
    if (e < E) {
        int d = dst[e];
        int s = src[e];
        if ((unsigned)d < (unsigned)n && (unsigned)s < (unsigned)n) {
            int p = g_off[d] + atomicAdd(&g_cur[d], 1);
            g_csr[p] = s;
        }
    }
}

// ---------------- mean aggregation (CSR, fp16 gather, fp32 accumulate) -------
__global__ void k_agg(int use_gh, int n) {
    int node = blockIdx.x * 8 + (threadIdx.x >> 5);
    int lane = threadIdx.x & 31;
    if (node >= n) return;
    const __half* feat = use_gh ? g_hh : g_xh;
    int beg = g_off[node];
    int end = g_off[node + 1];
    const __half* base = feat + (size_t)lane * 4;

    float4 a0 = {0.f, 0.f, 0.f, 0.f}, a1 = a0, a2 = a0, a3 = a0;
    int e = beg;
    for (; e + 4 <= end; e += 4) {
        int s0 = __ldg(&g_csr[e + 0]);
        int s1 = __ldg(&g_csr[e + 1]);
        int s2 = __ldg(&g_csr[e + 2]);
        int s3 = __ldg(&g_csr[e + 3]);
        uint2 u0 = *(const uint2*)(base + (size_t)s0 * F);
        uint2 u1 = *(const uint2*)(base + (size_t)s1 * F);
        uint2 u2 = *(const uint2*)(base + (size_t)s2 * F);
        uint2 u3 = *(const uint2*)(base + (size_t)s3 * F);
        float2 p, q;
        p = __half22float2(*(__half2*)&u0.x); q = __half22float2(*(__half2*)&u0.y);
        a0.x += p.x; a0.y += p.y; a0.z += q.x; a0.w += q.y;
        p = __half22float2(*(__half2*)&u1.x); q = __half22float2(*(__half2*)&u1.y);
        a1.x += p.x; a1.y += p.y; a1.z += q.x; a1.w += q.y;
        p = __half22float2(*(__half2*)&u2.x); q = __half22float2(*(__half2*)&u2.y);
        a2.x += p.x; a2.y += p.y; a2.z += q.x; a2.w += q.y;
        p = __half22float2(*(__half2*)&u3.x); q = __half22float2(*(__half2*)&u3.y);
        a3.x += p.x; a3.y += p.y; a3.z += q.x; a3.w += q.y;
    }
    for (; e < end; e++) {
        int s0 = __ldg(&g_csr[e]);
        uint2 u0 = *(const uint2*)(base + (size_t)s0 * F);
        float2 p = __half22float2(*(__half2*)&u0.x);
        float2 q = __half22float2(*(__half2*)&u0.y);
        a0.x += p.x; a0.y += p.y; a0.z += q.x; a0.w += q.y;
    }
    a0.x += a1.x + a2.x + a3.x;
    a0.y += a1.y + a2.y + a3.y;
    a0.z += a1.z + a2.z + a3.z;
    a0.w += a1.w + a2.w + a3.w;

    int deg = end - beg;
    float inv = 1.0f / (float)max(deg, 1);
    __half2 lo = __floats2half2_rn(a0.x * inv, a0.y * inv);
    __half2 hi = __floats2half2_rn(a0.z * inv, a0.w * inv);
    uint2 u;
    u.x = *(uint32_t*)&lo;
    u.y = *(uint32_t*)&hi;
    *(uint2*)(g_meanh + (size_t)node * F + lane * 4) = u;
}

// ---------------- weight prep (both layers): g_wth[l][n][k] -------------------
__global__ void k_prep(const float* __restrict__ Wl1, const float* __restrict__ Wr1,
                       const float* __restrict__ Wl2, const float* __restrict__ Wr2) {
    int idx = blockIdx.x * 256 + threadIdx.x;   // 2*32768 total
    if (idx >= 2 * 128 * 256) return;
    int l  = idx >> 15;
    int nn = (idx >> 8) & 127;
    int k  = idx & 255;
    const float* Wl = l ? Wl2 : Wl1;
    const float* Wr = l ? Wr2 : Wr1;
    float v = (k < 128) ? Wl[k * 128 + nn] : Wr[(k - 128) * 128 + nn];
    g_wth[l][nn * 256 + k] = __float2half_rn(v);
}

// ---------------- fp16 mma.sync dual GEMM (ldmatrix + cp.async pipeline) -----
// D[128r][128c] = [mean | self](K=256, fp16) @ g_wth[l]^T, fp32 acc, +bias, relu.
// 8 warps (4 m x 2 n), each warp 32x64 via m16n8k16. Double-buffered chunks.
__global__ __launch_bounds__(256) void k_gemm_mma(
    const float* __restrict__ bias,
    float* __restrict__ out_g, int layer, int n)
{
    __shared__ uint32_t sA[2][128][20];   // 16 used + 4 pad (80B row stride)
    __shared__ uint32_t sB[2][128][20];
    __shared__ float sBias[128];

    const __half* selfp = layer ? g_hh : g_xh;
    const __half* wt = g_wth[layer];

    int t = threadIdx.x;
    int warp = t >> 5;
    int lane = t & 31;
    int warp_m = warp & 3;
    int warp_n = warp >> 2;
    int group = lane >> 2;
    int tig = lane & 3;
    int lrow = lane & 15;          // ldmatrix row select
    int lksel = lane >> 4;         // ldmatrix k-half select
    int row0 = blockIdx.x * 128;

    if (t < 128) sBias[t] = bias[t];

    // staging geometry: thread covers (row=t>>2 and row+64), c4 = (t&3)
    int srow = t >> 2;
    int sc4 = t & 3;               // uint4 slot -> halves sc4*8, u32 sc4*4
    int r_g0 = row0 + srow;
    int r_g1 = row0 + srow + 64;

    // issue cp.async staging of chunk ch into buffer b
    auto stage = [&](int ch, int b) {
        const __half* srcp = (ch < 4) ? g_meanh : selfp;
        int kcol = (ch & 3) * 32 + sc4 * 8;
        int r0c = (r_g0 < n) ? r_g0 : 0;
        int r1c = (r_g1 < n) ? r_g1 : 0;
        cp16(saddr(&sA[b][srow][sc4 * 4]),
             srcp + (size_t)r0c * F + kcol, (r_g0 < n) ? 16 : 0);
        cp16(saddr(&sA[b][srow + 64][sc4 * 4]),
             srcp + (size_t)r1c * F + kcol, (r_g1 < n) ? 16 : 0);
        const __half* wsrc = wt + (ch & 7) * 32 + sc4 * 8;
        cp16(saddr(&sB[b][srow][sc4 * 4]), wsrc + srow * 256, 16);
        cp16(saddr(&sB[b][srow + 64][sc4 * 4]), wsrc + (srow + 64) * 256, 16);
        cp_commit();
    };

    float acc[2][8][4];
#pragma unroll
    for (int i = 0; i < 2; i++)
#pragma unroll
        for (int j = 0; j < 8; j++)
#pragma unroll
            for (int q = 0; q < 4; q++) acc[i][j][q] = 0.f;

    stage(0, 0);
    cp_wait0();
    __syncthreads();

#pragma unroll
    for (int ch = 0; ch < 8; ch++) {
        int buf = ch & 1;
        if (ch < 7) stage(ch + 1, buf ^ 1);

#pragma unroll
        for (int ks = 0; ks < 2; ks++) {
            uint32_t a[2][4];
#pragma unroll
            for (int mf = 0; mf < 2; mf++) {
                ldsm4(a[mf], saddr(&sA[buf][warp_m * 32 + mf * 16 + lrow]
                                      [ks * 8 + lksel * 4]));
            }
            uint32_t bf[8][2];
#pragma unroll
            for (int nfp = 0; nfp < 4; nfp++) {
                uint32_t r4[4];
                ldsm4(r4, saddr(&sB[buf][warp_n * 64 + nfp * 16 + lrow]
                                   [ks * 8 + lksel * 4]));
                bf[nfp * 2][0] = r4[0];
                bf[nfp * 2 + 1][0] = r4[1];
                bf[nfp * 2][1] = r4[2];
                bf[nfp * 2 + 1][1] = r4[3];
            }
#pragma unroll
            for (int mf = 0; mf < 2; mf++)
#pragma unroll
                for (int nf = 0; nf < 8; nf++)
                    mma_f16(acc[mf][nf], a[mf], bf[nf]);
        }

        if (ch < 7) {
            cp_wait0();
            __syncthreads();
        }
    }

    // epilogue
#pragma unroll
    for (int mf = 0; mf < 2; mf++) {
        int r_lo = row0 + warp_m * 32 + mf * 16 + group;
        int r_hi = r_lo + 8;
#pragma unroll
        for (int nf = 0; nf < 8; nf++) {
            int cc = warp_n * 64 + nf * 8 + tig * 2;
            float2 lo, hi;
            lo.x = acc[mf][nf][0] + sBias[cc];
            lo.y = acc[mf][nf][1] + sBias[cc + 1];
            hi.x = acc[mf][nf][2] + sBias[cc];
            hi.y = acc[mf][nf][3] + sBias[cc + 1];
            if (layer == 0) {   // relu + fp16 store to g_hh
                lo.x = fmaxf(lo.x, 0.f); lo.y = fmaxf(lo.y, 0.f);
                hi.x = fmaxf(hi.x, 0.f); hi.y = fmaxf(hi.y, 0.f);
                __half2 l2 = __floats2half2_rn(lo.x, lo.y);
                __half2 h2 = __floats2half2_rn(hi.x, hi.y);
                if (r_lo < n) *(__half2*)&g_hh[(size_t)r_lo * F + cc] = l2;
                if (r_hi < n) *(__half2*)&g_hh[(size_t)r_hi * F + cc] = h2;
            } else {            // fp32 store to harness out
                if (r_lo < n) *(float2*)&out_g[(size_t)r_lo * F + cc] = lo;
                if (r_hi < n) *(float2*)&out_g[(size_t)r_hi * F + cc] = hi;
            }
        }
    }
}

// ---------------- launch: kernel launches ONLY -------------------------------
extern "C" void kernel_launch(void* const* d_in, const int* in_sizes, int n_in,
                              void* d_out, int out_size) {
    const float* x   = (const float*)d_in[0];
    const int*   ei  = (const int*)d_in[1];   // int32 [2, E]
    const float* Wl1 = (const float*)d_in[2];
    const float* Wr1 = (const float*)d_in[3];
    const float* b1  = (const float*)d_in[4];
    const float* Wl2 = (const float*)d_in[5];
    const float* Wr2 = (const float*)d_in[6];
    const float* b2  = (const float*)d_in[7];
    float* out = (float*)d_out;

    int n = in_sizes[0] / F;
    int E = in_sizes[1] / 2;
    if (n > MAXN) n = MAXN;
    if (E > MAXE) E = MAXE;

    const int* src = ei;
    const int* dst = ei + E;

    int nb = (n + 255) / 256;

    // 1) init + CSR build + weight prep
    k_init<<<(n * 32 + 255) / 256, 256>>>(x, n);
    k_hist<<<(E + 255) / 256, 256>>>(dst, E, n);
    k_prep<<<256, 256>>>(Wl1, Wr1, Wl2, Wr2);
    k_blksum<<<nb, 256>>>(n);
    k_blkscan<<<1, 512>>>(nb, n);
    k_scanout<<<nb, 256>>>(n);
    k_scatter<<<(E + 255) / 256, 256>>>(src, dst, E, n);

    int agg_grid  = (n + 7) / 8;
    int gemm_grid = (n + 127) / 128;

    // 2) layer 1
    k_agg<<<agg_grid, 256>>>(0, n);
    k_gemm_mma<<<gemm_grid, 256>>>(b1, nullptr, 0, n);

    // 3) layer 2
    k_agg<<<agg_grid, 256>>>(1, n);
    k_gemm_mma<<<gemm_grid, 256>>>(b2, out, 1, n);
}

// round 12
// speedup vs baseline: 4.1195x; 1.0116x over previous
#include <cuda_runtime.h>
#include <cuda_fp16.h>
#include <cstdint>

#define MAXN 100000
#define MAXE 1600000
#define F 128

// ---------------- scratch (static device globals; no allocs allowed) ----------
__device__ int    g_cnt[MAXN];
__device__ int    g_off[MAXN + 1];
__device__ int    g_rank[MAXE];                // per-edge rank within dst bucket
__device__ int    g_csr[MAXE];
__device__ int    g_blk[512];
__device__ int    g_blkoff[512];
__device__ __half g_xh[(size_t)MAXN * F];      // fp16 copy of x
__device__ __half g_hh[(size_t)MAXN * F];      // fp16 layer-1 activations
__device__ __half g_meanh[(size_t)MAXN * F];   // fp16 aggregated means
__device__ __half g_wth[2][128 * 256];         // per-layer [n][k] = fp16(concat(Wl,Wr)[k][n])

// ---------------- helpers ----------------------------------------------------
__device__ __forceinline__ void mma_f16(float* c, const uint32_t* a, const uint32_t* b) {
    asm volatile(
        "mma.sync.aligned.m16n8k16.row.col.f32.f16.f16.f32 "
        "{%0,%1,%2,%3}, {%4,%5,%6,%7}, {%8,%9}, {%0,%1,%2,%3};"
        : "+f"(c[0]), "+f"(c[1]), "+f"(c[2]), "+f"(c[3])
        : "r"(a[0]), "r"(a[1]), "r"(a[2]), "r"(a[3]), "r"(b[0]), "r"(b[1]));
}
__device__ __forceinline__ void ldsm4(uint32_t* r, uint32_t addr) {
    asm volatile("ldmatrix.sync.aligned.m8n8.x4.shared.b16 {%0,%1,%2,%3}, [%4];"
                 : "=r"(r[0]), "=r"(r[1]), "=r"(r[2]), "=r"(r[3]) : "r"(addr));
}
__device__ __forceinline__ uint32_t saddr(const void* p) {
    return (uint32_t)__cvta_generic_to_shared(p);
}
__device__ __forceinline__ void cp16(uint32_t dst, const void* src, int src_bytes) {
    asm volatile("cp.async.ca.shared.global [%0], [%1], 16, %2;"
                 :: "r"(dst), "l"(src), "r"(src_bytes) : "memory");
}
__device__ __forceinline__ void cp_commit() {
    asm volatile("cp.async.commit_group;" ::: "memory");
}
__device__ __forceinline__ void cp_wait0() {
    asm volatile("cp.async.wait_group 0;" ::: "memory");
}

// ---------------- CSR build --------------------------------------------------
__global__ void k_zero(int n) {
    int i = blockIdx.x * 256 + threadIdx.x;
    if (i < n) g_cnt[i] = 0;
}

// histogram; atomic return value = per-bucket rank (free rank assignment)
__global__ void k_hist(const int* __restrict__ dst, int E, int n) {
    int e = blockIdx.x * 256 + threadIdx.x;
    if (e < E) {
        int d = dst[e];
        int r = 0;
        if ((unsigned)d < (unsigned)n) r = atomicAdd(&g_cnt[d], 1);
        g_rank[e] = r;
    }
}

__global__ void k_blksum(int n) {
    __shared__ int sh[256];
    int b = blockIdx.x, t = threadIdx.x;
    int i = b * 256 + t;
    sh[t] = (i < n) ? g_cnt[i] : 0;
    __syncthreads();
    for (int s = 128; s > 0; s >>= 1) {
        if (t < s) sh[t] += sh[t + s];
        __syncthreads();
    }
    if (t == 0) g_blk[b] = sh[0];
}

__global__ void k_blkscan(int nb, int n) {
    __shared__ int sh[512];
    int t = threadIdx.x;
    int v = (t < nb) ? g_blk[t] : 0;
    sh[t] = v;
    __syncthreads();
    for (int d = 1; d < 512; d <<= 1) {
        int u = (t >= d) ? sh[t - d] : 0;
        __syncthreads();
        sh[t] += u;
        __syncthreads();
    }
    g_blkoff[t] = sh[t] - v;
    if (t == 511) g_off[n] = sh[511];
}

__global__ void k_scanout(int n) {
    __shared__ int sh[256];
    int b = blockIdx.x, t = threadIdx.x;
    int i = b * 256 + t;
    int c = (i < n) ? g_cnt[i] : 0;
    sh[t] = c;
    __syncthreads();
    for (int d = 1; d < 256; d <<= 1) {
        int u = (t >= d) ? sh[t - d] : 0;
        __syncthreads();
        sh[t] += u;
        __syncthreads();
    }
    if (i < n) g_off[i] = g_blkoff[b] + sh[t] - c;
}

// atomic-free scatter: position = offset[dst] + rank (from hist)
__global__ void k_scatter(const int* __restrict__ src,
                          const int* __restrict__ dst, int E, int n) {
    int e = blockIdx.x * 256 + threadIdx.x;
    if (e < E) {
        int d = dst[e];
        int s = src[e];
        if ((unsigned)d < (unsigned)n && (unsigned)s < (unsigned)n) {
            g_csr[g_off[d] + g_rank[e]] = s;
        }
    }
}

// ---------------- x -> fp16 (overlapped stream) -------------------------------
__global__ void k_x2h(const float* __restrict__ x, int n) {
    int i = blockIdx.x * 256 + threadIdx.x;
    if (i < n * 32) {
        float4 v = ((const float4*)x)[i];
        __half2 lo = __floats2half2_rn(v.x, v.y);
        __half2 hi = __floats2half2_rn(v.z, v.w);
        uint2 u;
        u.x = *(uint32_t*)&lo;
        u.y = *(uint32_t*)&hi;
        ((uint2*)g_xh)[i] = u;
    }
}

// ---------------- mean aggregation (CSR, fp16 gather, fp32 accumulate) -------
__global__ void k_agg(int use_gh, int n) {
    int node = blockIdx.x * 8 + (threadIdx.x >> 5);
    int lane = threadIdx.x & 31;
    if (node >= n) return;
    const __half* feat = use_gh ? g_hh : g_xh;
    int beg = g_off[node];
    int end = g_off[node + 1];
    const __half* base = feat + (size_t)lane * 4;

    float4 a0 = {0.f, 0.f, 0.f, 0.f}, a1 = a0, a2 = a0, a3 = a0;
    int e = beg;
    for (; e + 4 <= end; e += 4) {
        int s0 = __ldg(&g_csr[e + 0]);
        int s1 = __ldg(&g_csr[e + 1]);
        int s2 = __ldg(&g_csr[e + 2]);
        int s3 = __ldg(&g_csr[e + 3]);
        uint2 u0 = *(const uint2*)(base + (size_t)s0 * F);
        uint2 u1 = *(const uint2*)(base + (size_t)s1 * F);
        uint2 u2 = *(const uint2*)(base + (size_t)s2 * F);
        uint2 u3 = *(const uint2*)(base + (size_t)s3 * F);
        float2 p, q;
        p = __half22float2(*(__half2*)&u0.x); q = __half22float2(*(__half2*)&u0.y);
        a0.x += p.x; a0.y += p.y; a0.z += q.x; a0.w += q.y;
        p = __half22float2(*(__half2*)&u1.x); q = __half22float2(*(__half2*)&u1.y);
        a1.x += p.x; a1.y += p.y; a1.z += q.x; a1.w += q.y;
        p = __half22float2(*(__half2*)&u2.x); q = __half22float2(*(__half2*)&u2.y);
        a2.x += p.x; a2.y += p.y; a2.z += q.x; a2.w += q.y;
        p = __half22float2(*(__half2*)&u3.x); q = __half22float2(*(__half2*)&u3.y);
        a3.x += p.x; a3.y += p.y; a3.z += q.x; a3.w += q.y;
    }
    for (; e < end; e++) {
        int s0 = __ldg(&g_csr[e]);
        uint2 u0 = *(const uint2*)(base + (size_t)s0 * F);
        float2 p = __half22float2(*(__half2*)&u0.x);
        float2 q = __half22float2(*(__half2*)&u0.y);
        a0.x += p.x; a0.y += p.y; a0.z += q.x; a0.w += q.y;
    }
    a0.x += a1.x + a2.x + a3.x;
    a0.y += a1.y + a2.y + a3.y;
    a0.z += a1.z + a2.z + a3.z;
    a0.w += a1.w + a2.w + a3.w;

    int deg = end - beg;
    float inv = 1.0f / (float)max(deg, 1);
    __half2 lo = __floats2half2_rn(a0.x * inv, a0.y * inv);
    __half2 hi = __floats2half2_rn(a0.z * inv, a0.w * inv);
    uint2 u;
    u.x = *(uint32_t*)&lo;
    u.y = *(uint32_t*)&hi;
    *(uint2*)(g_meanh + (size_t)node * F + lane * 4) = u;
}

// ---------------- weight prep (both layers): g_wth[l][n][k] -------------------
__global__ void k_prep(const float* __restrict__ Wl1, const float* __restrict__ Wr1,
                       const float* __restrict__ Wl2, const float* __restrict__ Wr2) {
    int idx = blockIdx.x * 256 + threadIdx.x;   // 2*32768 total
    if (idx >= 2 * 128 * 256) return;
    int l  = idx >> 15;
    int nn = (idx >> 8) & 127;
    int k  = idx & 255;
    const float* Wl = l ? Wl2 : Wl1;
    const float* Wr = l ? Wr2 : Wr1;
    float v = (k < 128) ? Wl[k * 128 + nn] : Wr[(k - 128) * 128 + nn];
    g_wth[l][nn * 256 + k] = __float2half_rn(v);
}

// ---------------- fp16 mma.sync dual GEMM (ldmatrix + cp.async pipeline) -----
__global__ __launch_bounds__(256) void k_gemm_mma(
    const float* __restrict__ bias,
    float* __restrict__ out_g, int layer, int n)
{
    __shared__ uint32_t sA[2][128][20];   // 16 used + 4 pad (80B row stride)
    __shared__ uint32_t sB[2][128][20];
    __shared__ float sBias[128];

    const __half* selfp = layer ? g_hh : g_xh;
    const __half* wt = g_wth[layer];

    int t = threadIdx.x;
    int warp = t >> 5;
    int lane = t & 31;
    int warp_m = warp & 3;
    int warp_n = warp >> 2;
    int group = lane >> 2;
    int tig = lane & 3;
    int lrow = lane & 15;
    int lksel = lane >> 4;
    int row0 = blockIdx.x * 128;

    if (t < 128) sBias[t] = bias[t];

    int srow = t >> 2;
    int sc4 = t & 3;
    int r_g0 = row0 + srow;
    int r_g1 = row0 + srow + 64;

    auto stage = [&](int ch, int b) {
        const __half* srcp = (ch < 4) ? g_meanh : selfp;
        int kcol = (ch & 3) * 32 + sc4 * 8;
        int r0c = (r_g0 < n) ? r_g0 : 0;
        int r1c = (r_g1 < n) ? r_g1 : 0;
        cp16(saddr(&sA[b][srow][sc4 * 4]),
             srcp + (size_t)r0c * F + kcol, (r_g0 < n) ? 16 : 0);
        cp16(saddr(&sA[b][srow + 64][sc4 * 4]),
             srcp + (size_t)r1c * F + kcol, (r_g1 < n) ? 16 : 0);
        const __half* wsrc = wt + (ch & 7) * 32 + sc4 * 8;
        cp16(saddr(&sB[b][srow][sc4 * 4]), wsrc + srow * 256, 16);
        cp16(saddr(&sB[b][srow + 64][sc4 * 4]), wsrc + (srow + 64) * 256, 16);
        cp_commit();
    };

    float acc[2][8][4];
#pragma unroll
    for (int i = 0; i < 2; i++)
#pragma unroll
        for (int j = 0; j < 8; j++)
#pragma unroll
            for (int q = 0; q < 4; q++) acc[i][j][q] = 0.f;

    stage(0, 0);
    cp_wait0();
    __syncthreads();

#pragma unroll
    for (int ch = 0; ch < 8; ch++) {
        int buf = ch & 1;
        if (ch < 7) stage(ch + 1, buf ^ 1);

#pragma unroll
        for (int ks = 0; ks < 2; ks++) {
            uint32_t a[2][4];
#pragma unroll
            for (int mf = 0; mf < 2; mf++) {
                ldsm4(a[mf], saddr(&sA[buf][warp_m * 32 + mf * 16 + lrow]
                                      [ks * 8 + lksel * 4]));
            }
            uint32_t bf[8][2];
#pragma unroll
            for (int nfp = 0; nfp < 4; nfp++) {
                uint32_t r4[4];
                ldsm4(r4, saddr(&sB[buf][warp_n * 64 + nfp * 16 + lrow]
                                   [ks * 8 + lksel * 4]));
                bf[nfp * 2][0] = r4[0];
                bf[nfp * 2 + 1][0] = r4[1];
                bf[nfp * 2][1] = r4[2];
                bf[nfp * 2 + 1][1] = r4[3];
            }
#pragma unroll
            for (int mf = 0; mf < 2; mf++)
#pragma unroll
                for (int nf = 0; nf < 8; nf++)
                    mma_f16(acc[mf][nf], a[mf], bf[nf]);
        }

        if (ch < 7) {
            cp_wait0();
            __syncthreads();
        }
    }

    // epilogue
#pragma unroll
    for (int mf = 0; mf < 2; mf++) {
        int r_lo = row0 + warp_m * 32 + mf * 16 + group;
        int r_hi = r_lo + 8;
#pragma unroll
        for (int nf = 0; nf < 8; nf++) {
            int cc = warp_n * 64 + nf * 8 + tig * 2;
            float2 lo, hi;
            lo.x = acc[mf][nf][0] + sBias[cc];
            lo.y = acc[mf][nf][1] + sBias[cc + 1];
            hi.x = acc[mf][nf][2] + sBias[cc];
            hi.y = acc[mf][nf][3] + sBias[cc + 1];
            if (layer == 0) {
                lo.x = fmaxf(lo.x, 0.f); lo.y = fmaxf(lo.y, 0.f);
                hi.x = fmaxf(hi.x, 0.f); hi.y = fmaxf(hi.y, 0.f);
                __half2 l2 = __floats2half2_rn(lo.x, lo.y);
                __half2 h2 = __floats2half2_rn(hi.x, hi.y);
                if (r_lo < n) *(__half2*)&g_hh[(size_t)r_lo * F + cc] = l2;
                if (r_hi < n) *(__half2*)&g_hh[(size_t)r_hi * F + cc] = h2;
            } else {
                if (r_lo < n) *(float2*)&out_g[(size_t)r_lo * F + cc] = lo;
                if (r_hi < n) *(float2*)&out_g[(size_t)r_hi * F + cc] = hi;
            }
        }
    }
}

// ---------------- launch: kernel launches + capture-safe stream fork ----------
extern "C" void kernel_launch(void* const* d_in, const int* in_sizes, int n_in,
                              void* d_out, int out_size) {
    const float* x   = (const float*)d_in[0];
    const int*   ei  = (const int*)d_in[1];   // int32 [2, E]
    const float* Wl1 = (const float*)d_in[2];
    const float* Wr1 = (const float*)d_in[3];
    const float* b1  = (const float*)d_in[4];
    const float* Wl2 = (const float*)d_in[5];
    const float* Wr2 = (const float*)d_in[6];
    const float* b2  = (const float*)d_in[7];
    float* out = (float*)d_out;

    int n = in_sizes[0] / F;
    int E = in_sizes[1] / 2;
    if (n > MAXN) n = MAXN;
    if (E > MAXE) E = MAXE;

    const int* src = ei;
    const int* dst = ei + E;

    int nb = (n + 255) / 256;

    // fork a side stream (host-side resources only; created/destroyed per call)
    cudaStream_t s1;
    cudaStreamCreateWithFlags(&s1, cudaStreamNonBlocking);
    cudaEvent_t evFork, evJoin;
    cudaEventCreateWithFlags(&evFork, cudaEventDisableTiming);
    cudaEventCreateWithFlags(&evJoin, cudaEventDisableTiming);

    cudaEventRecord(evFork, 0);
    cudaStreamWaitEvent(s1, evFork, 0);

    // side stream: x->fp16 + weight prep (independent of CSR chain)
    k_x2h<<<(n * 32 + 255) / 256, 256, 0, s1>>>(x, n);
    k_prep<<<256, 256, 0, s1>>>(Wl1, Wr1, Wl2, Wr2);
    cudaEventRecord(evJoin, s1);

    // main stream: CSR build (hist computes ranks; scatter is atomic-free)
    k_zero<<<nb, 256>>>(n);
    k_hist<<<(E + 255) / 256, 256>>>(dst, E, n);
    k_blksum<<<nb, 256>>>(n);
    k_blkscan<<<1, 512>>>(nb, n);
    k_scanout<<<nb, 256>>>(n);
    k_scatter<<<(E + 255) / 256, 256>>>(src, dst, E, n);

    // join: aggregation needs g_xh, GEMM needs g_wth
    cudaStreamWaitEvent(0, evJoin, 0);

    int agg_grid  = (n + 7) / 8;
    int gemm_grid = (n + 127) / 128;

    // layer 1
    k_agg<<<agg_grid, 256>>>(0, n);
    k_gemm_mma<<<gemm_grid, 256>>>(b1, nullptr, 0, n);

    // layer 2
    k_agg<<<agg_grid, 256>>>(1, n);
    k_gemm_mma<<<gemm_grid, 256>>>(b2, out, 1, n);

    cudaEventDestroy(evFork);
    cudaEventDestroy(evJoin);
    cudaStreamDestroy(s1);
}

// round 13
// speedup vs baseline: 4.1310x; 1.0028x over previous
#include <cuda_runtime.h>
#include <cuda_fp16.h>
#include <cstdint>

#define MAXN 100000
#define MAXE 1600000
#define F 128

// ---------------- scratch (static device globals; no allocs allowed) ----------
__device__ int    g_cnt[MAXN];
__device__ int    g_off[MAXN + 1];
__device__ int    g_rank[MAXE];                // per-edge rank within dst bucket
__device__ int    g_csr[MAXE];
__device__ int    g_blk[512];
__device__ int    g_blkoff[512];
__device__ __half g_xh[(size_t)MAXN * F];      // fp16 copy of x
__device__ __half g_hh[(size_t)MAXN * F];      // fp16 layer-1 activations
__device__ __half g_meanh[(size_t)MAXN * F];   // fp16 aggregated means
__device__ __half g_wth[2][128 * 256];         // per-layer [n][k] = fp16(concat(Wl,Wr)[k][n])

// ---------------- helpers ----------------------------------------------------
__device__ __forceinline__ void mma_f16(float* c, const uint32_t* a, const uint32_t* b) {
    asm volatile(
        "mma.sync.aligned.m16n8k16.row.col.f32.f16.f16.f32 "
        "{%0,%1,%2,%3}, {%4,%5,%6,%7}, {%8,%9}, {%0,%1,%2,%3};"
        : "+f"(c[0]), "+f"(c[1]), "+f"(c[2]), "+f"(c[3])
        : "r"(a[0]), "r"(a[1]), "r"(a[2]), "r"(a[3]), "r"(b[0]), "r"(b[1]));
}
__device__ __forceinline__ void ldsm4(uint32_t* r, uint32_t addr) {
    asm volatile("ldmatrix.sync.aligned.m8n8.x4.shared.b16 {%0,%1,%2,%3}, [%4];"
                 : "=r"(r[0]), "=r"(r[1]), "=r"(r[2]), "=r"(r[3]) : "r"(addr));
}
__device__ __forceinline__ uint32_t saddr(const void* p) {
    return (uint32_t)__cvta_generic_to_shared(p);
}
__device__ __forceinline__ void cp16(uint32_t dst, const void* src, int src_bytes) {
    asm volatile("cp.async.ca.shared.global [%0], [%1], 16, %2;"
                 :: "r"(dst), "l"(src), "r"(src_bytes) : "memory");
}
__device__ __forceinline__ void cp_commit() {
    asm volatile("cp.async.commit_group;" ::: "memory");
}
__device__ __forceinline__ void cp_wait0() {
    asm volatile("cp.async.wait_group 0;" ::: "memory");
}

// ---------------- CSR build --------------------------------------------------
__global__ void k_zero(int n) {
    int i = blockIdx.x * 256 + threadIdx.x;       // int4 slots
    if (i * 4 < n) {
        int4 z = make_int4(0, 0, 0, 0);
        *(int4*)&g_cnt[i * 4] = z;                // MAXN rounded handling: pad write ok? No.
    }
}

// histogram, 4 edges/thread (MLP=4 on the returning atomics)
__global__ void k_hist(const int* __restrict__ dst, int E, int n) {
    int e = (blockIdx.x * 256 + threadIdx.x) * 4;
    if (e + 4 <= E) {
        int4 d = *(const int4*)(dst + e);
        int4 r = make_int4(0, 0, 0, 0);
        if ((unsigned)d.x < (unsigned)n) r.x = atomicAdd(&g_cnt[d.x], 1);
        if ((unsigned)d.y < (unsigned)n) r.y = atomicAdd(&g_cnt[d.y], 1);
        if ((unsigned)d.z < (unsigned)n) r.z = atomicAdd(&g_cnt[d.z], 1);
        if ((unsigned)d.w < (unsigned)n) r.w = atomicAdd(&g_cnt[d.w], 1);
        *(int4*)(g_rank + e) = r;
    } else {
        for (; e < E; e++) {
            int d = dst[e];
            int r = 0;
            if ((unsigned)d < (unsigned)n) r = atomicAdd(&g_cnt[d], 1);
            g_rank[e] = r;
        }
    }
}

__global__ void k_blksum(int n) {
    __shared__ int sh[256];
    int b = blockIdx.x, t = threadIdx.x;
    int i = b * 256 + t;
    sh[t] = (i < n) ? g_cnt[i] : 0;
    __syncthreads();
    for (int s = 128; s > 0; s >>= 1) {
        if (t < s) sh[t] += sh[t + s];
        __syncthreads();
    }
    if (t == 0) g_blk[b] = sh[0];
}

__global__ void k_blkscan(int nb, int n) {
    __shared__ int sh[512];
    int t = threadIdx.x;
    int v = (t < nb) ? g_blk[t] : 0;
    sh[t] = v;
    __syncthreads();
    for (int d = 1; d < 512; d <<= 1) {
        int u = (t >= d) ? sh[t - d] : 0;
        __syncthreads();
        sh[t] += u;
        __syncthreads();
    }
    g_blkoff[t] = sh[t] - v;
    if (t == 511) g_off[n] = sh[511];
}

__global__ void k_scanout(int n) {
    __shared__ int sh[256];
    int b = blockIdx.x, t = threadIdx.x;
    int i = b * 256 + t;
    int c = (i < n) ? g_cnt[i] : 0;
    sh[t] = c;
    __syncthreads();
    for (int d = 1; d < 256; d <<= 1) {
        int u = (t >= d) ? sh[t - d] : 0;
        __syncthreads();
        sh[t] += u;
        __syncthreads();
    }
    if (i < n) g_off[i] = g_blkoff[b] + sh[t] - c;
}

// atomic-free scatter, 4 edges/thread: position = offset[dst] + rank
__global__ void k_scatter(const int* __restrict__ src,
                          const int* __restrict__ dst, int E, int n) {
    int e = (blockIdx.x * 256 + threadIdx.x) * 4;
    if (e + 4 <= E) {
        int4 d = *(const int4*)(dst + e);
        int4 s = *(const int4*)(src + e);
        int4 r = *(const int4*)(g_rank + e);
        int o0 = ((unsigned)d.x < (unsigned)n) ? g_off[d.x] : -1;
        int o1 = ((unsigned)d.y < (unsigned)n) ? g_off[d.y] : -1;
        int o2 = ((unsigned)d.z < (unsigned)n) ? g_off[d.z] : -1;
        int o3 = ((unsigned)d.w < (unsigned)n) ? g_off[d.w] : -1;
        if (o0 >= 0 && (unsigned)s.x < (unsigned)n) g_csr[o0 + r.x] = s.x;
        if (o1 >= 0 && (unsigned)s.y < (unsigned)n) g_csr[o1 + r.y] = s.y;
        if (o2 >= 0 && (unsigned)s.z < (unsigned)n) g_csr[o2 + r.z] = s.z;
        if (o3 >= 0 && (unsigned)s.w < (unsigned)n) g_csr[o3 + r.w] = s.w;
    } else {
        for (; e < E; e++) {
            int d = dst[e];
            int s = src[e];
            if ((unsigned)d < (unsigned)n && (unsigned)s < (unsigned)n)
                g_csr[g_off[d] + g_rank[e]] = s;
        }
    }
}

// ---------------- x -> fp16 (overlapped stream) -------------------------------
__global__ void k_x2h(const float* __restrict__ x, int n) {
    int i = blockIdx.x * 256 + threadIdx.x;
    if (i < n * 32) {
        float4 v = ((const float4*)x)[i];
        __half2 lo = __floats2half2_rn(v.x, v.y);
        __half2 hi = __floats2half2_rn(v.z, v.w);
        uint2 u;
        u.x = *(uint32_t*)&lo;
        u.y = *(uint32_t*)&hi;
        ((uint2*)g_xh)[i] = u;
    }
}

// ---------------- mean aggregation (CSR, fp16 gather, fp32 accumulate) -------
__global__ void k_agg(int use_gh, int n) {
    int node = blockIdx.x * 8 + (threadIdx.x >> 5);
    int lane = threadIdx.x & 31;
    if (node >= n) return;
    const __half* feat = use_gh ? g_hh : g_xh;
    int beg = g_off[node];
    int end = g_off[node + 1];
    const __half* base = feat + (size_t)lane * 4;

    float4 a0 = {0.f, 0.f, 0.f, 0.f}, a1 = a0, a2 = a0, a3 = a0;
    int e = beg;
    for (; e + 4 <= end; e += 4) {
        int s0 = __ldg(&g_csr[e + 0]);
        int s1 = __ldg(&g_csr[e + 1]);
        int s2 = __ldg(&g_csr[e + 2]);
        int s3 = __ldg(&g_csr[e + 3]);
        uint2 u0 = *(const uint2*)(base + (size_t)s0 * F);
        uint2 u1 = *(const uint2*)(base + (size_t)s1 * F);
        uint2 u2 = *(const uint2*)(base + (size_t)s2 * F);
        uint2 u3 = *(const uint2*)(base + (size_t)s3 * F);
        float2 p, q;
        p = __half22float2(*(__half2*)&u0.x); q = __half22float2(*(__half2*)&u0.y);
        a0.x += p.x; a0.y += p.y; a0.z += q.x; a0.w += q.y;
        p = __half22float2(*(__half2*)&u1.x); q = __half22float2(*(__half2*)&u1.y);
        a1.x += p.x; a1.y += p.y; a1.z += q.x; a1.w += q.y;
        p = __half22float2(*(__half2*)&u2.x); q = __half22float2(*(__half2*)&u2.y);
        a2.x += p.x; a2.y += p.y; a2.z += q.x; a2.w += q.y;
        p = __half22float2(*(__half2*)&u3.x); q = __half22float2(*(__half2*)&u3.y);
        a3.x += p.x; a3.y += p.y; a3.z += q.x; a3.w += q.y;
    }
    for (; e < end; e++) {
        int s0 = __ldg(&g_csr[e]);
        uint2 u0 = *(const uint2*)(base + (size_t)s0 * F);
        float2 p = __half22float2(*(__half2*)&u0.x);
        float2 q = __half22float2(*(__half2*)&u0.y);
        a0.x += p.x; a0.y += p.y; a0.z += q.x; a0.w += q.y;
    }
    a0.x += a1.x + a2.x + a3.x;
    a0.y += a1.y + a2.y + a3.y;
    a0.z += a1.z + a2.z + a3.z;
    a0.w += a1.w + a2.w + a3.w;

    int deg = end - beg;
    float inv = 1.0f / (float)max(deg, 1);
    __half2 lo = __floats2half2_rn(a0.x * inv, a0.y * inv);
    __half2 hi = __floats2half2_rn(a0.z * inv, a0.w * inv);
    uint2 u;
    u.x = *(uint32_t*)&lo;
    u.y = *(uint32_t*)&hi;
    *(uint2*)(g_meanh + (size_t)node * F + lane * 4) = u;
}

// ---------------- weight prep (both layers): g_wth[l][n][k] -------------------
__global__ void k_prep(const float* __restrict__ Wl1, const float* __restrict__ Wr1,
                       const float* __restrict__ Wl2, const float* __restrict__ Wr2) {
    int idx = blockIdx.x * 256 + threadIdx.x;   // 2*32768 total
    if (idx >= 2 * 128 * 256) return;
    int l  = idx >> 15;
    int nn = (idx >> 8) & 127;
    int k  = idx & 255;
    const float* Wl = l ? Wl2 : Wl1;
    const float* Wr = l ? Wr2 : Wr1;
    float v = (k < 128) ? Wl[k * 128 + nn] : Wr[(k - 128) * 128 + nn];
    g_wth[l][nn * 256 + k] = __float2half_rn(v);
}

// ---------------- fp16 mma.sync dual GEMM (ldmatrix + cp.async pipeline) -----
__global__ __launch_bounds__(256) void k_gemm_mma(
    const float* __restrict__ bias,
    float* __restrict__ out_g, int layer, int n)
{
    __shared__ uint32_t sA[2][128][20];   // 16 used + 4 pad (80B row stride)
    __shared__ uint32_t sB[2][128][20];
    __shared__ float sBias[128];

    const __half* selfp = layer ? g_hh : g_xh;
    const __half* wt = g_wth[layer];

    int t = threadIdx.x;
    int warp = t >> 5;
    int lane = t & 31;
    int warp_m = warp & 3;
    int warp_n = warp >> 2;
    int group = lane >> 2;
    int tig = lane & 3;
    int lrow = lane & 15;
    int lksel = lane >> 4;
    int row0 = blockIdx.x * 128;

    if (t < 128) sBias[t] = bias[t];

    int srow = t >> 2;
    int sc4 = t & 3;
    int r_g0 = row0 + srow;
    int r_g1 = row0 + srow + 64;

    auto stage = [&](int ch, int b) {
        const __half* srcp = (ch < 4) ? g_meanh : selfp;
        int kcol = (ch & 3) * 32 + sc4 * 8;
        int r0c = (r_g0 < n) ? r_g0 : 0;
        int r1c = (r_g1 < n) ? r_g1 : 0;
        cp16(saddr(&sA[b][srow][sc4 * 4]),
             srcp + (size_t)r0c * F + kcol, (r_g0 < n) ? 16 : 0);
        cp16(saddr(&sA[b][srow + 64][sc4 * 4]),
             srcp + (size_t)r1c * F + kcol, (r_g1 < n) ? 16 : 0);
        const __half* wsrc = wt + (ch & 7) * 32 + sc4 * 8;
        cp16(saddr(&sB[b][srow][sc4 * 4]), wsrc + srow * 256, 16);
        cp16(saddr(&sB[b][srow + 64][sc4 * 4]), wsrc + (srow + 64) * 256, 16);
        cp_commit();
    };

    float acc[2][8][4];
#pragma unroll
    for (int i = 0; i < 2; i++)
#pragma unroll
        for (int j = 0; j < 8; j++)
#pragma unroll
            for (int q = 0; q < 4; q++) acc[i][j][q] = 0.f;

    stage(0, 0);
    cp_wait0();
    __syncthreads();

#pragma unroll
    for (int ch = 0; ch < 8; ch++) {
        int buf = ch & 1;
        if (ch < 7) stage(ch + 1, buf ^ 1);

#pragma unroll
        for (int ks = 0; ks < 2; ks++) {
            uint32_t a[2][4];
#pragma unroll
            for (int mf = 0; mf < 2; mf++) {
                ldsm4(a[mf], saddr(&sA[buf][warp_m * 32 + mf * 16 + lrow]
                                      [ks * 8 + lksel * 4]));
            }
            uint32_t bf[8][2];
#pragma unroll
            for (int nfp = 0; nfp < 4; nfp++) {
                uint32_t r4[4];
                ldsm4(r4, saddr(&sB[buf][warp_n * 64 + nfp * 16 + lrow]
                                   [ks * 8 + lksel * 4]));
                bf[nfp * 2][0] = r4[0];
                bf[nfp * 2 + 1][0] = r4[1];
                bf[nfp * 2][1] = r4[2];
                bf[nfp * 2 + 1][1] = r4[3];
            }
#pragma unroll
            for (int mf = 0; mf < 2; mf++)
#pragma unroll
                for (int nf = 0; nf < 8; nf++)
                    mma_f16(acc[mf][nf], a[mf], bf[nf]);
        }

        if (ch < 7) {
            cp_wait0();
            __syncthreads();
        }
    }

    // epilogue
#pragma unroll
    for (int mf = 0; mf < 2; mf++) {
        int r_lo = row0 + warp_m * 32 + mf * 16 + group;
        int r_hi = r_lo + 8;
#pragma unroll
        for (int nf = 0; nf < 8; nf++) {
            int cc = warp_n * 64 + nf * 8 + tig * 2;
            float2 lo, hi;
            lo.x = acc[mf][nf][0] + sBias[cc];
            lo.y = acc[mf][nf][1] + sBias[cc + 1];
            hi.x = acc[mf][nf][2] + sBias[cc];
            hi.y = acc[mf][nf][3] + sBias[cc + 1];
            if (layer == 0) {
                lo.x = fmaxf(lo.x, 0.f); lo.y = fmaxf(lo.y, 0.f);
                hi.x = fmaxf(hi.x, 0.f); hi.y = fmaxf(hi.y, 0.f);
                __half2 l2 = __floats2half2_rn(lo.x, lo.y);
                __half2 h2 = __floats2half2_rn(hi.x, hi.y);
                if (r_lo < n) *(__half2*)&g_hh[(size_t)r_lo * F + cc] = l2;
                if (r_hi < n) *(__half2*)&g_hh[(size_t)r_hi * F + cc] = h2;
            } else {
                if (r_lo < n) *(float2*)&out_g[(size_t)r_lo * F + cc] = lo;
                if (r_hi < n) *(float2*)&out_g[(size_t)r_hi * F + cc] = hi;
            }
        }
    }
}

// ---------------- launch: kernel launches + capture-safe stream fork ----------
extern "C" void kernel_launch(void* const* d_in, const int* in_sizes, int n_in,
                              void* d_out, int out_size) {
    const float* x   = (const float*)d_in[0];
    const int*   ei  = (const int*)d_in[1];   // int32 [2, E]
    const float* Wl1 = (const float*)d_in[2];
    const float* Wr1 = (const float*)d_in[3];
    const float* b1  = (const float*)d_in[4];
    const float* Wl2 = (const float*)d_in[5];
    const float* Wr2 = (const float*)d_in[6];
    const float* b2  = (const float*)d_in[7];
    float* out = (float*)d_out;

    int n = in_sizes[0] / F;
    int E = in_sizes[1] / 2;
    if (n > MAXN) n = MAXN;
    if (E > MAXE) E = MAXE;

    const int* src = ei;
    const int* dst = ei + E;

    int nb = (n + 255) / 256;
    int nq = (n + 1023) / 1024;          // int4 zero blocks
    int eq = (E + 1023) / 1024;          // 4-edge-per-thread blocks

    // fork a side stream (host-side resources only; created/destroyed per call)
    cudaStream_t s1;
    cudaStreamCreateWithFlags(&s1, cudaStreamNonBlocking);
    cudaEvent_t evFork, evJoin;
    cudaEventCreateWithFlags(&evFork, cudaEventDisableTiming);
    cudaEventCreateWithFlags(&evJoin, cudaEventDisableTiming);

    cudaEventRecord(evFork, 0);
    cudaStreamWaitEvent(s1, evFork, 0);

    // side stream: x->fp16 + weight prep (independent of CSR chain)
    k_x2h<<<(n * 32 + 255) / 256, 256, 0, s1>>>(x, n);
    k_prep<<<256, 256, 0, s1>>>(Wl1, Wr1, Wl2, Wr2);
    cudaEventRecord(evJoin, s1);

    // main stream: CSR build (hist computes ranks; scatter is atomic-free)
    k_zero<<<nq, 256>>>((n + 3) & ~3);
    k_hist<<<eq, 256>>>(dst, E, n);
    k_blksum<<<nb, 256>>>(n);
    k_blkscan<<<1, 512>>>(nb, n);
    k_scanout<<<nb, 256>>>(n);
    k_scatter<<<eq, 256>>>(src, dst, E, n);

    // join: aggregation needs g_xh, GEMM needs g_wth
    cudaStreamWaitEvent(0, evJoin, 0);

    int agg_grid  = (n + 7) / 8;
    int gemm_grid = (n + 127) / 128;

    // layer 1
    k_agg<<<agg_grid, 256>>>(0, n);
    k_gemm_mma<<<gemm_grid, 256>>>(b1, nullptr, 0, n);

    // layer 2
    k_agg<<<agg_grid, 256>>>(1, n);
    k_gemm_mma<<<gemm_grid, 256>>>(b2, out, 1, n);

    cudaEventDestroy(evFork);
    cudaEventDestroy(evJoin);
    cudaStreamDestroy(s1);
}